// round 5
// baseline (speedup 1.0000x reference)
#include <cuda_runtime.h>
#include <cstddef>

#define BB 32
#define TT 2048
#define DD 512
#define HH 512
#define G4 2048
#define NCTA 128
#define JC 4

// Scratch (device globals are the sanctioned allocation-free scratch)
__device__ float g_i2h[(size_t)BB * TT * G4];   // 512 MB, layer-0 i2h
__device__ float g_hbuf0[2][HH * BB];           // double-buffered h0, [j][b]
__device__ float g_hbuf1[2][HH * BB];           // double-buffered h1, [j][b]
__device__ unsigned g_bar;
__device__ unsigned g_epoch;

__global__ void init_state_kernel() {
    int i = blockIdx.x * blockDim.x + threadIdx.x;
    if (i < HH * BB) { g_hbuf0[0][i] = 0.f; g_hbuf1[0][i] = 0.f; }
    if (i == 0) { g_bar = 0u; g_epoch = 0u; }
}

__device__ __forceinline__ float sigf(float x) { return 1.f / (1.f + __expf(-x)); }
__device__ __forceinline__ float tanhf_(float x) {
    x = fminf(15.f, fmaxf(-15.f, x));
    float e = __expf(2.f * x);
    return (e - 1.f) / (e + 1.f);
}

// C[M,2048] = A[M,512] @ W[2048,512]^T + bias ; M = 65536, tiles 128x128x16.
__global__ __launch_bounds__(256, 2) void gemm_kernel(
    const float* __restrict__ A, const float* __restrict__ W,
    const float* __restrict__ bias, float* __restrict__ C)
{
    __shared__ float As[2][16][128];
    __shared__ float Ws[2][16][128];
    const int tid = threadIdx.x;
    const int tx = tid & 15, ty = tid >> 4;
    const int m0 = blockIdx.y * 128, n0 = blockIdx.x * 128;

    float acc[8][8];
    #pragma unroll
    for (int i = 0; i < 8; i++)
        #pragma unroll
        for (int j = 0; j < 8; j++) acc[i][j] = 0.f;

    const int lr = tid >> 1;
    const int lc = (tid & 1) * 2;
    const float* Arow = A + (size_t)(m0 + lr) * DD;
    const float* Wrow = W + (size_t)(n0 + lr) * DD;

    float4 ra0, ra1, rw0, rw1;
    ra0 = *reinterpret_cast<const float4*>(&Arow[lc * 4]);
    ra1 = *reinterpret_cast<const float4*>(&Arow[(lc + 1) * 4]);
    rw0 = *reinterpret_cast<const float4*>(&Wrow[lc * 4]);
    rw1 = *reinterpret_cast<const float4*>(&Wrow[(lc + 1) * 4]);
    {
        int c0 = lc, c1 = lc + 1;
        As[0][c0*4+0][lr] = ra0.x; As[0][c0*4+1][lr] = ra0.y;
        As[0][c0*4+2][lr] = ra0.z; As[0][c0*4+3][lr] = ra0.w;
        As[0][c1*4+0][lr] = ra1.x; As[0][c1*4+1][lr] = ra1.y;
        As[0][c1*4+2][lr] = ra1.z; As[0][c1*4+3][lr] = ra1.w;
        Ws[0][c0*4+0][lr] = rw0.x; Ws[0][c0*4+1][lr] = rw0.y;
        Ws[0][c0*4+2][lr] = rw0.z; Ws[0][c0*4+3][lr] = rw0.w;
        Ws[0][c1*4+0][lr] = rw1.x; Ws[0][c1*4+1][lr] = rw1.y;
        Ws[0][c1*4+2][lr] = rw1.z; Ws[0][c1*4+3][lr] = rw1.w;
    }
    __syncthreads();

    int p = 0;
    for (int k0 = 0; k0 < DD; k0 += 16) {
        const bool more = (k0 + 16 < DD);
        if (more) {
            ra0 = *reinterpret_cast<const float4*>(&Arow[k0 + 16 + lc * 4]);
            ra1 = *reinterpret_cast<const float4*>(&Arow[k0 + 16 + (lc + 1) * 4]);
            rw0 = *reinterpret_cast<const float4*>(&Wrow[k0 + 16 + lc * 4]);
            rw1 = *reinterpret_cast<const float4*>(&Wrow[k0 + 16 + (lc + 1) * 4]);
        }
        #pragma unroll
        for (int k = 0; k < 16; k++) {
            float4 a0 = *reinterpret_cast<const float4*>(&As[p][k][ty * 8]);
            float4 a1 = *reinterpret_cast<const float4*>(&As[p][k][ty * 8 + 4]);
            float4 b0 = *reinterpret_cast<const float4*>(&Ws[p][k][tx * 8]);
            float4 b1 = *reinterpret_cast<const float4*>(&Ws[p][k][tx * 8 + 4]);
            float av[8] = {a0.x,a0.y,a0.z,a0.w,a1.x,a1.y,a1.z,a1.w};
            float bv[8] = {b0.x,b0.y,b0.z,b0.w,b1.x,b1.y,b1.z,b1.w};
            #pragma unroll
            for (int i = 0; i < 8; i++)
                #pragma unroll
                for (int j = 0; j < 8; j++)
                    acc[i][j] = fmaf(av[i], bv[j], acc[i][j]);
        }
        if (more) {
            int q = 1 - p;
            int c0 = lc, c1 = lc + 1;
            As[q][c0*4+0][lr] = ra0.x; As[q][c0*4+1][lr] = ra0.y;
            As[q][c0*4+2][lr] = ra0.z; As[q][c0*4+3][lr] = ra0.w;
            As[q][c1*4+0][lr] = ra1.x; As[q][c1*4+1][lr] = ra1.y;
            As[q][c1*4+2][lr] = ra1.z; As[q][c1*4+3][lr] = ra1.w;
            Ws[q][c0*4+0][lr] = rw0.x; Ws[q][c0*4+1][lr] = rw0.y;
            Ws[q][c0*4+2][lr] = rw0.z; Ws[q][c0*4+3][lr] = rw0.w;
            Ws[q][c1*4+0][lr] = rw1.x; Ws[q][c1*4+1][lr] = rw1.y;
            Ws[q][c1*4+2][lr] = rw1.z; Ws[q][c1*4+3][lr] = rw1.w;
            __syncthreads();
            p = q;
        }
    }

    float4 bs0 = *reinterpret_cast<const float4*>(&bias[n0 + tx*8]);
    float4 bs1 = *reinterpret_cast<const float4*>(&bias[n0 + tx*8 + 4]);
    #pragma unroll
    for (int i = 0; i < 8; i++) {
        size_t row = (size_t)(m0 + ty*8 + i) * G4 + n0 + tx*8;
        float4 o0 = make_float4(acc[i][0]+bs0.x, acc[i][1]+bs0.y, acc[i][2]+bs0.z, acc[i][3]+bs0.w);
        float4 o1 = make_float4(acc[i][4]+bs1.x, acc[i][5]+bs1.y, acc[i][6]+bs1.z, acc[i][7]+bs1.w);
        *reinterpret_cast<float4*>(&C[row])     = o0;
        *reinterpret_cast<float4*>(&C[row + 4]) = o1;
    }
}

// Fused two-layer pipelined recurrence. 128 CTAs, CTA owns 4 hidden units of
// BOTH layers. Wall step s: L0 computes t=s, L1 computes t=s-1 (2049 steps,
// ONE global barrier each — half the barrier count of the split scheme).
// L1's i2h GEMM (y0@Wi1^T) is folded into its k-loop (k=0..1023 over [y0;h1]).
__global__ __launch_bounds__(256, 1) void lstm_fused_kernel(
    const float* __restrict__ Wh0, const float* __restrict__ bh0,
    const float* __restrict__ Wi1, const float* __restrict__ bi1,
    const float* __restrict__ Wh1, const float* __restrict__ bh1,
    const float* __restrict__ i2h, float* __restrict__ yout,
    float* __restrict__ hc_out)
{
    extern __shared__ float sm[];
    float* ws0  = sm;                   // 512*16
    float* ws1  = ws0 + 512 * 16;       // 1024*16
    float* red0 = ws1 + 1024 * 16;      // 512*8
    float* red1 = red0 + 512 * 8;       // 512*8
    float* bs0  = red1 + 512 * 8;       // 16
    float* bs1  = bs0 + 16;             // 16
    float* cs0  = bs1 + 16;             // 128
    float* cs1  = cs0 + 128;            // 128

    const int tid = threadIdx.x;
    const int j0 = blockIdx.x * JC;

    {   // stage weights transposed: ws[k][rl], rl = g*4 + jj
        int rl = tid >> 4;
        int g = rl >> 2, jj = rl & 3;
        int k0 = (tid & 15) * 32;
        const float* w0row = Wh0 + (size_t)(g * HH + j0 + jj) * HH;
        const float* wirow = Wi1 + (size_t)(g * HH + j0 + jj) * HH;
        const float* whrow = Wh1 + (size_t)(g * HH + j0 + jj) * HH;
        #pragma unroll 8
        for (int kk = 0; kk < 32; kk++) {
            ws0[(k0 + kk) * 16 + rl]         = w0row[k0 + kk];
            ws1[(k0 + kk) * 16 + rl]         = wirow[k0 + kk];
            ws1[(512 + k0 + kk) * 16 + rl]   = whrow[k0 + kk];
        }
        if (tid < 16) {
            int gg = tid >> 2, jx = tid & 3;
            bs0[tid] = bh0[gg * HH + j0 + jx];
            bs1[tid] = bi1[gg * HH + j0 + jx] + bh1[gg * HH + j0 + jx];
        }
        if (tid < 128) { cs0[tid] = 0.f; cs1[tid] = 0.f; }
    }
    __syncthreads();

    const int ks = tid >> 5;           // warp id 0..7
    const int rt = (tid >> 3) & 3;     // row quad
    const int bt = tid & 7;            // batch quad
    const float4* ws0_4 = reinterpret_cast<const float4*>(ws0);
    const float4* ws1_4 = reinterpret_cast<const float4*>(ws1);

    for (int s = 0; s <= TT; s++) {
        float pre0 = 0.f, pre1 = 0.f, pre2 = 0.f, pre3 = 0.f;

        // ---- Phase A: L0 FMA (t = s), k = 0..511, 64 k per warp ----
        if (s < TT) {
            if (tid < 128) {   // i2h prefetch for tail0
                const int b_ = tid & 31, jj_ = tid >> 5;
                const float* irow = i2h + ((size_t)b_ * TT + s) * G4 + j0 + jj_;
                pre0 = __ldcg(irow);
                pre1 = __ldcg(irow + HH);
                pre2 = __ldcg(irow + 2 * HH);
                pre3 = __ldcg(irow + 3 * HH);
            }
            const float4* hsrc4 = reinterpret_cast<const float4*>(g_hbuf0[s & 1]);
            const int kb = ks * 64;
            float acc[4][4];
            #pragma unroll
            for (int ri = 0; ri < 4; ri++)
                #pragma unroll
                for (int bi = 0; bi < 4; bi++) acc[ri][bi] = 0.f;
            #pragma unroll
            for (int c = 0; c < 8; c++) {
                float4 hp[8];
                #pragma unroll
                for (int i = 0; i < 8; i++)
                    hp[i] = __ldcg(&hsrc4[(size_t)(kb + c * 8 + i) * 8 + bt]);
                #pragma unroll
                for (int i = 0; i < 8; i++) {
                    float4 wv = ws0_4[(kb + c * 8 + i) * 4 + rt];
                    acc[0][0] = fmaf(wv.x, hp[i].x, acc[0][0]);
                    acc[0][1] = fmaf(wv.x, hp[i].y, acc[0][1]);
                    acc[0][2] = fmaf(wv.x, hp[i].z, acc[0][2]);
                    acc[0][3] = fmaf(wv.x, hp[i].w, acc[0][3]);
                    acc[1][0] = fmaf(wv.y, hp[i].x, acc[1][0]);
                    acc[1][1] = fmaf(wv.y, hp[i].y, acc[1][1]);
                    acc[1][2] = fmaf(wv.y, hp[i].z, acc[1][2]);
                    acc[1][3] = fmaf(wv.y, hp[i].w, acc[1][3]);
                    acc[2][0] = fmaf(wv.z, hp[i].x, acc[2][0]);
                    acc[2][1] = fmaf(wv.z, hp[i].y, acc[2][1]);
                    acc[2][2] = fmaf(wv.z, hp[i].z, acc[2][2]);
                    acc[2][3] = fmaf(wv.z, hp[i].w, acc[2][3]);
                    acc[3][0] = fmaf(wv.w, hp[i].x, acc[3][0]);
                    acc[3][1] = fmaf(wv.w, hp[i].y, acc[3][1]);
                    acc[3][2] = fmaf(wv.w, hp[i].z, acc[3][2]);
                    acc[3][3] = fmaf(wv.w, hp[i].w, acc[3][3]);
                }
            }
            #pragma unroll
            for (int ri = 0; ri < 4; ri++)
                #pragma unroll
                for (int bi = 0; bi < 4; bi++)
                    red0[((rt * 4 + ri) * 32 + bt * 4 + bi) * 8 + ks] = acc[ri][bi];
        }

        // ---- Phase B: L1 FMA (t = s-1), k = 0..1023, 128 k per warp ----
        // warps 0-3: y0(t) part (from g_hbuf0[s&1]); warps 4-7: h1(t-1) part
        if (s >= 1) {
            const bool isY = (ks < 4);
            const float4* src4 = reinterpret_cast<const float4*>(
                isY ? g_hbuf0[s & 1] : g_hbuf1[(s - 1) & 1]);
            const int kb  = (isY ? ks : ks - 4) * 128;      // index into src
            const int kw  = (isY ? 0 : 512) + kb;           // index into ws1
            float acc[4][4];
            #pragma unroll
            for (int ri = 0; ri < 4; ri++)
                #pragma unroll
                for (int bi = 0; bi < 4; bi++) acc[ri][bi] = 0.f;
            #pragma unroll
            for (int c = 0; c < 16; c++) {
                float4 hp[8];
                #pragma unroll
                for (int i = 0; i < 8; i++)
                    hp[i] = __ldcg(&src4[(size_t)(kb + c * 8 + i) * 8 + bt]);
                #pragma unroll
                for (int i = 0; i < 8; i++) {
                    float4 wv = ws1_4[(kw + c * 8 + i) * 4 + rt];
                    acc[0][0] = fmaf(wv.x, hp[i].x, acc[0][0]);
                    acc[0][1] = fmaf(wv.x, hp[i].y, acc[0][1]);
                    acc[0][2] = fmaf(wv.x, hp[i].z, acc[0][2]);
                    acc[0][3] = fmaf(wv.x, hp[i].w, acc[0][3]);
                    acc[1][0] = fmaf(wv.y, hp[i].x, acc[1][0]);
                    acc[1][1] = fmaf(wv.y, hp[i].y, acc[1][1]);
                    acc[1][2] = fmaf(wv.y, hp[i].z, acc[1][2]);
                    acc[1][3] = fmaf(wv.y, hp[i].w, acc[1][3]);
                    acc[2][0] = fmaf(wv.z, hp[i].x, acc[2][0]);
                    acc[2][1] = fmaf(wv.z, hp[i].y, acc[2][1]);
                    acc[2][2] = fmaf(wv.z, hp[i].z, acc[2][2]);
                    acc[2][3] = fmaf(wv.z, hp[i].w, acc[2][3]);
                    acc[3][0] = fmaf(wv.w, hp[i].x, acc[3][0]);
                    acc[3][1] = fmaf(wv.w, hp[i].y, acc[3][1]);
                    acc[3][2] = fmaf(wv.w, hp[i].z, acc[3][2]);
                    acc[3][3] = fmaf(wv.w, hp[i].w, acc[3][3]);
                }
            }
            #pragma unroll
            for (int ri = 0; ri < 4; ri++)
                #pragma unroll
                for (int bi = 0; bi < 4; bi++)
                    red1[((rt * 4 + ri) * 32 + bt * 4 + bi) * 8 + ks] = acc[ri][bi];
        }
        __syncthreads();

        // ---- Phase C: parallel tails (tid<128 -> L0, tid>=128 -> L1) ----
        if (tid < 128) {
            if (s < TT) {
                const int b = tid & 31, jj = tid >> 5;
                const int j = j0 + jj;
                float pre[4] = {pre0, pre1, pre2, pre3};
                float gate[4];
                #pragma unroll
                for (int g = 0; g < 4; g++) {
                    const int rr = g * 4 + jj;
                    const float4* rp = reinterpret_cast<const float4*>(&red0[(rr * 32 + b) * 8]);
                    float4 q0 = rp[0], q1 = rp[1];
                    gate[g] = ((q0.x + q0.y) + (q0.z + q0.w))
                            + ((q1.x + q1.y) + (q1.z + q1.w))
                            + pre[g] + bs0[rr];
                }
                float ig = sigf(gate[0]);
                float fg = sigf(gate[1]);
                float cg = tanhf_(gate[2]);
                float og = sigf(gate[3]);
                float c_new = fmaf(fg, cs0[tid], ig * cg);
                float h_new = og * tanhf_(c_new);
                cs0[tid] = c_new;
                g_hbuf0[(s + 1) & 1][j * BB + b] = h_new;
                if (s == TT - 1) {
                    hc_out[(size_t)0 * BB * HH + b * HH + j] = h_new;   // h layer0
                    hc_out[(size_t)2 * BB * HH + b * HH + j] = c_new;   // c layer0
                }
            }
        } else {
            if (s >= 1) {
                const int tt_ = tid - 128;
                const int b = tt_ & 31, jj = tt_ >> 5;
                const int j = j0 + jj;
                const int t = s - 1;
                float gate[4];
                #pragma unroll
                for (int g = 0; g < 4; g++) {
                    const int rr = g * 4 + jj;
                    const float4* rp = reinterpret_cast<const float4*>(&red1[(rr * 32 + b) * 8]);
                    float4 q0 = rp[0], q1 = rp[1];
                    gate[g] = ((q0.x + q0.y) + (q0.z + q0.w))
                            + ((q1.x + q1.y) + (q1.z + q1.w))
                            + bs1[rr];
                }
                float ig = sigf(gate[0]);
                float fg = sigf(gate[1]);
                float cg = tanhf_(gate[2]);
                float og = sigf(gate[3]);
                float c_new = fmaf(fg, cs1[tt_], ig * cg);
                float h_new = og * tanhf_(c_new);
                cs1[tt_] = c_new;
                g_hbuf1[s & 1][j * BB + b] = h_new;
                yout[((size_t)b * TT + t) * HH + j] = h_new;            // y1 [B,T,H]
                if (t == TT - 1) {
                    hc_out[(size_t)1 * BB * HH + b * HH + j] = h_new;   // h layer1
                    hc_out[(size_t)3 * BB * HH + b * HH + j] = c_new;   // c layer1
                }
            }
        }

        // ---- global barrier (skip after the last wall step) ----
        if (s < TT) {
            __syncthreads();
            if (tid == 0) {
                const unsigned target = (unsigned)(s + 1) * NCTA;
                unsigned prev;
                asm volatile("atom.release.gpu.add.u32 %0, [%1], %2;"
                             : "=r"(prev) : "l"(&g_bar), "r"(1u) : "memory");
                if (prev + 1u == target) {
                    asm volatile("st.release.gpu.u32 [%0], %1;"
                                 :: "l"(&g_epoch), "r"((unsigned)(s + 1)) : "memory");
                } else {
                    unsigned e;
                    do {
                        asm volatile("ld.acquire.gpu.u32 %0, [%1];"
                                     : "=r"(e) : "l"(&g_epoch) : "memory");
                    } while (e < (unsigned)(s + 1));
                }
            }
            __syncthreads();
        }
    }
}

extern "C" void kernel_launch(void* const* d_in, const int* in_sizes, int n_in,
                              void* d_out, int out_size)
{
    (void)in_sizes; (void)n_in; (void)out_size;
    const float* x   = (const float*)d_in[0];
    const float* Wi0 = (const float*)d_in[1];
    const float* bi0 = (const float*)d_in[2];
    const float* Wh0 = (const float*)d_in[3];
    const float* bh0 = (const float*)d_in[4];
    const float* Wi1 = (const float*)d_in[5];
    const float* bi1 = (const float*)d_in[6];
    const float* Wh1 = (const float*)d_in[7];
    const float* bh1 = (const float*)d_in[8];
    float* out = (float*)d_out;

    float* i2h_p;
    cudaGetSymbolAddress((void**)&i2h_p, g_i2h);

    const int SMEM = (512*16 + 1024*16 + 512*8 + 512*8 + 16 + 16 + 128 + 128)
                     * (int)sizeof(float);
    cudaFuncSetAttribute(lstm_fused_kernel,
                         cudaFuncAttributeMaxDynamicSharedMemorySize, SMEM);

    dim3 ggrid(G4 / 128, (BB * TT) / 128);
    float* hc = out + (size_t)BB * TT * HH;

    gemm_kernel<<<ggrid, 256>>>(x, Wi0, bi0, i2h_p);          // L0 i2h only
    init_state_kernel<<<64, 256>>>();
    lstm_fused_kernel<<<NCTA, 256, SMEM>>>(Wh0, bh0, Wi1, bi1, Wh1, bh1,
                                           i2h_p, out, hc);
}

// round 6
// speedup vs baseline: 1.6978x; 1.6978x over previous
#include <cuda_runtime.h>
#include <cstddef>

#define BB 32
#define TT 2048
#define DD 512
#define HH 512
#define G4 2048
#define NCTA 128
#define JC 4
#define NTHR 384

// Scratch (device globals are the sanctioned allocation-free scratch)
__device__ float g_i2h[(size_t)BB * TT * G4];   // 512 MB, layer-0 i2h
__device__ float g_hbuf0[2][HH * BB];           // double-buffered h0, [j][b]
__device__ float g_hbuf1[2][HH * BB];           // double-buffered h1, [j][b]
__device__ unsigned g_flags[NCTA * 32];         // per-CTA arrival, own 128B line
__device__ unsigned g_epoch;

__global__ void init_state_kernel() {
    int i = blockIdx.x * blockDim.x + threadIdx.x;
    if (i < HH * BB) { g_hbuf0[0][i] = 0.f; g_hbuf1[0][i] = 0.f; }
    if (i < NCTA * 32) g_flags[i] = 0u;
    if (i == 0) g_epoch = 0u;
}

__device__ __forceinline__ float sigf(float x) { return 1.f / (1.f + __expf(-x)); }
__device__ __forceinline__ float tanhf_(float x) {
    x = fminf(15.f, fmaxf(-15.f, x));
    float e = __expf(2.f * x);
    return (e - 1.f) / (e + 1.f);
}

// C[M,2048] = A[M,512] @ W[2048,512]^T + bias ; M = 65536, tiles 128x128x16.
__global__ __launch_bounds__(256, 2) void gemm_kernel(
    const float* __restrict__ A, const float* __restrict__ W,
    const float* __restrict__ bias, float* __restrict__ C)
{
    __shared__ float As[2][16][128];
    __shared__ float Ws[2][16][128];
    const int tid = threadIdx.x;
    const int tx = tid & 15, ty = tid >> 4;
    const int m0 = blockIdx.y * 128, n0 = blockIdx.x * 128;

    float acc[8][8];
    #pragma unroll
    for (int i = 0; i < 8; i++)
        #pragma unroll
        for (int j = 0; j < 8; j++) acc[i][j] = 0.f;

    const int lr = tid >> 1;
    const int lc = (tid & 1) * 2;
    const float* Arow = A + (size_t)(m0 + lr) * DD;
    const float* Wrow = W + (size_t)(n0 + lr) * DD;

    float4 ra0, ra1, rw0, rw1;
    ra0 = *reinterpret_cast<const float4*>(&Arow[lc * 4]);
    ra1 = *reinterpret_cast<const float4*>(&Arow[(lc + 1) * 4]);
    rw0 = *reinterpret_cast<const float4*>(&Wrow[lc * 4]);
    rw1 = *reinterpret_cast<const float4*>(&Wrow[(lc + 1) * 4]);
    {
        int c0 = lc, c1 = lc + 1;
        As[0][c0*4+0][lr] = ra0.x; As[0][c0*4+1][lr] = ra0.y;
        As[0][c0*4+2][lr] = ra0.z; As[0][c0*4+3][lr] = ra0.w;
        As[0][c1*4+0][lr] = ra1.x; As[0][c1*4+1][lr] = ra1.y;
        As[0][c1*4+2][lr] = ra1.z; As[0][c1*4+3][lr] = ra1.w;
        Ws[0][c0*4+0][lr] = rw0.x; Ws[0][c0*4+1][lr] = rw0.y;
        Ws[0][c0*4+2][lr] = rw0.z; Ws[0][c0*4+3][lr] = rw0.w;
        Ws[0][c1*4+0][lr] = rw1.x; Ws[0][c1*4+1][lr] = rw1.y;
        Ws[0][c1*4+2][lr] = rw1.z; Ws[0][c1*4+3][lr] = rw1.w;
    }
    __syncthreads();

    int p = 0;
    for (int k0 = 0; k0 < DD; k0 += 16) {
        const bool more = (k0 + 16 < DD);
        if (more) {
            ra0 = *reinterpret_cast<const float4*>(&Arow[k0 + 16 + lc * 4]);
            ra1 = *reinterpret_cast<const float4*>(&Arow[k0 + 16 + (lc + 1) * 4]);
            rw0 = *reinterpret_cast<const float4*>(&Wrow[k0 + 16 + lc * 4]);
            rw1 = *reinterpret_cast<const float4*>(&Wrow[k0 + 16 + (lc + 1) * 4]);
        }
        #pragma unroll
        for (int k = 0; k < 16; k++) {
            float4 a0 = *reinterpret_cast<const float4*>(&As[p][k][ty * 8]);
            float4 a1 = *reinterpret_cast<const float4*>(&As[p][k][ty * 8 + 4]);
            float4 b0 = *reinterpret_cast<const float4*>(&Ws[p][k][tx * 8]);
            float4 b1 = *reinterpret_cast<const float4*>(&Ws[p][k][tx * 8 + 4]);
            float av[8] = {a0.x,a0.y,a0.z,a0.w,a1.x,a1.y,a1.z,a1.w};
            float bv[8] = {b0.x,b0.y,b0.z,b0.w,b1.x,b1.y,b1.z,b1.w};
            #pragma unroll
            for (int i = 0; i < 8; i++)
                #pragma unroll
                for (int j = 0; j < 8; j++)
                    acc[i][j] = fmaf(av[i], bv[j], acc[i][j]);
        }
        if (more) {
            int q = 1 - p;
            int c0 = lc, c1 = lc + 1;
            As[q][c0*4+0][lr] = ra0.x; As[q][c0*4+1][lr] = ra0.y;
            As[q][c0*4+2][lr] = ra0.z; As[q][c0*4+3][lr] = ra0.w;
            As[q][c1*4+0][lr] = ra1.x; As[q][c1*4+1][lr] = ra1.y;
            As[q][c1*4+2][lr] = ra1.z; As[q][c1*4+3][lr] = ra1.w;
            Ws[q][c0*4+0][lr] = rw0.x; Ws[q][c0*4+1][lr] = rw0.y;
            Ws[q][c0*4+2][lr] = rw0.z; Ws[q][c0*4+3][lr] = rw0.w;
            Ws[q][c1*4+0][lr] = rw1.x; Ws[q][c1*4+1][lr] = rw1.y;
            Ws[q][c1*4+2][lr] = rw1.z; Ws[q][c1*4+3][lr] = rw1.w;
            __syncthreads();
            p = q;
        }
    }

    float4 bs0 = *reinterpret_cast<const float4*>(&bias[n0 + tx*8]);
    float4 bs1 = *reinterpret_cast<const float4*>(&bias[n0 + tx*8 + 4]);
    #pragma unroll
    for (int i = 0; i < 8; i++) {
        size_t row = (size_t)(m0 + ty*8 + i) * G4 + n0 + tx*8;
        float4 o0 = make_float4(acc[i][0]+bs0.x, acc[i][1]+bs0.y, acc[i][2]+bs0.z, acc[i][3]+bs0.w);
        float4 o1 = make_float4(acc[i][4]+bs1.x, acc[i][5]+bs1.y, acc[i][6]+bs1.z, acc[i][7]+bs1.w);
        *reinterpret_cast<float4*>(&C[row])     = o0;
        *reinterpret_cast<float4*>(&C[row + 4]) = o1;
    }
}

// Fused two-layer pipelined recurrence, SPATIAL phase split.
// 384 threads / 12 warps: warps 0-3 -> L0 (t=s), warps 4-11 -> L1 (t=s-1).
// Every warp runs ONE 128-k-iter loop (R4's proven shape). 2049 wall steps,
// one parallel-detection global barrier each.
__global__ __launch_bounds__(NTHR, 1) void lstm_fused_kernel(
    const float* __restrict__ Wh0, const float* __restrict__ bh0,
    const float* __restrict__ Wi1, const float* __restrict__ bi1,
    const float* __restrict__ Wh1, const float* __restrict__ bh1,
    const float* __restrict__ i2h, float* __restrict__ yout,
    float* __restrict__ hc_out)
{
    extern __shared__ float sm[];
    float* ws0  = sm;                   // 512*16
    float* ws1  = ws0 + 512 * 16;       // 1024*16
    float* red0 = ws1 + 1024 * 16;      // 16*32*4
    float* red1 = red0 + 16 * 32 * 4;   // 16*32*8
    float* bs0  = red1 + 16 * 32 * 8;   // 16
    float* bs1  = bs0 + 16;             // 16
    float* cs0  = bs1 + 16;             // 128
    float* cs1  = cs0 + 128;            // 128

    const int tid = threadIdx.x;
    const int bid = blockIdx.x;
    const int j0 = bid * JC;

    // ---- stage weights transposed: ws[k*16 + rl], rl = g*4 + jj ----
    for (int idx = tid; idx < 512 * 16; idx += NTHR) {
        int k = idx >> 4, rl = idx & 15;
        int g = rl >> 2, jj = rl & 3;
        ws0[idx] = Wh0[(size_t)(g * HH + j0 + jj) * HH + k];
    }
    for (int idx = tid; idx < 1024 * 16; idx += NTHR) {
        int k = idx >> 4, rl = idx & 15;
        int g = rl >> 2, jj = rl & 3;
        ws1[idx] = (k < 512)
            ? Wi1[(size_t)(g * HH + j0 + jj) * HH + k]
            : Wh1[(size_t)(g * HH + j0 + jj) * HH + (k - 512)];
    }
    if (tid < 16) {
        int gg = tid >> 2, jx = tid & 3;
        bs0[tid] = bh0[gg * HH + j0 + jx];
        bs1[tid] = bi1[gg * HH + j0 + jx] + bh1[gg * HH + j0 + jx];
    }
    if (tid < 128) { cs0[tid] = 0.f; cs1[tid] = 0.f; }
    __syncthreads();

    const int w  = tid >> 5;           // warp 0..11
    const int rt = (tid >> 3) & 3;     // row quad
    const int bt = tid & 7;            // batch quad
    const float4* ws0_4 = reinterpret_cast<const float4*>(ws0);
    const float4* ws1_4 = reinterpret_cast<const float4*>(ws1);

    for (int s = 0; s <= TT; s++) {
        float pre0 = 0.f, pre1 = 0.f, pre2 = 0.f, pre3 = 0.f;
        if (tid < 128 && s < TT) {   // i2h prefetch for L0 tail
            const int b_ = tid & 31, jj_ = tid >> 5;
            const float* irow = i2h + ((size_t)b_ * TT + s) * G4 + j0 + jj_;
            pre0 = __ldcg(irow);
            pre1 = __ldcg(irow + HH);
            pre2 = __ldcg(irow + 2 * HH);
            pre3 = __ldcg(irow + 3 * HH);
        }

        // ---- FMA phase: one 128-k loop per warp ----
        {
            const float4* src4 = nullptr;
            const float4* wsrc4 = nullptr;
            int kb = 0, kw = 0;
            bool active = false;
            if (w < 4) {                 // L0, t = s
                if (s < TT) {
                    active = true;
                    src4 = reinterpret_cast<const float4*>(g_hbuf0[s & 1]);
                    kb = w * 128;  kw = kb;  wsrc4 = ws0_4;
                }
            } else if (s >= 1) {         // L1, t = s-1
                active = true;
                wsrc4 = ws1_4;
                if (w < 8) {             // y0(t) part
                    src4 = reinterpret_cast<const float4*>(g_hbuf0[s & 1]);
                    kb = (w - 4) * 128;  kw = kb;
                } else {                 // h1(t-1) part
                    src4 = reinterpret_cast<const float4*>(g_hbuf1[(s - 1) & 1]);
                    kb = (w - 8) * 128;  kw = 512 + kb;
                }
            }
            if (active) {
                float acc[4][4];
                #pragma unroll
                for (int ri = 0; ri < 4; ri++)
                    #pragma unroll
                    for (int bi = 0; bi < 4; bi++) acc[ri][bi] = 0.f;
                #pragma unroll 2
                for (int c = 0; c < 16; c++) {        // 16 chunks x 8 k
                    float4 hp[8];
                    #pragma unroll
                    for (int i = 0; i < 8; i++)
                        hp[i] = __ldcg(&src4[(size_t)(kb + c * 8 + i) * 8 + bt]);
                    #pragma unroll
                    for (int i = 0; i < 8; i++) {
                        float4 wv = wsrc4[(kw + c * 8 + i) * 4 + rt];
                        acc[0][0] = fmaf(wv.x, hp[i].x, acc[0][0]);
                        acc[0][1] = fmaf(wv.x, hp[i].y, acc[0][1]);
                        acc[0][2] = fmaf(wv.x, hp[i].z, acc[0][2]);
                        acc[0][3] = fmaf(wv.x, hp[i].w, acc[0][3]);
                        acc[1][0] = fmaf(wv.y, hp[i].x, acc[1][0]);
                        acc[1][1] = fmaf(wv.y, hp[i].y, acc[1][1]);
                        acc[1][2] = fmaf(wv.y, hp[i].z, acc[1][2]);
                        acc[1][3] = fmaf(wv.y, hp[i].w, acc[1][3]);
                        acc[2][0] = fmaf(wv.z, hp[i].x, acc[2][0]);
                        acc[2][1] = fmaf(wv.z, hp[i].y, acc[2][1]);
                        acc[2][2] = fmaf(wv.z, hp[i].z, acc[2][2]);
                        acc[2][3] = fmaf(wv.z, hp[i].w, acc[2][3]);
                        acc[3][0] = fmaf(wv.w, hp[i].x, acc[3][0]);
                        acc[3][1] = fmaf(wv.w, hp[i].y, acc[3][1]);
                        acc[3][2] = fmaf(wv.w, hp[i].z, acc[3][2]);
                        acc[3][3] = fmaf(wv.w, hp[i].w, acc[3][3]);
                    }
                }
                if (w < 4) {
                    #pragma unroll
                    for (int ri = 0; ri < 4; ri++)
                        #pragma unroll
                        for (int bi = 0; bi < 4; bi++)
                            red0[((rt * 4 + ri) * 32 + bt * 4 + bi) * 4 + w] = acc[ri][bi];
                } else {
                    #pragma unroll
                    for (int ri = 0; ri < 4; ri++)
                        #pragma unroll
                        for (int bi = 0; bi < 4; bi++)
                            red1[((rt * 4 + ri) * 32 + bt * 4 + bi) * 8 + (w - 4)] = acc[ri][bi];
                }
            }
        }
        __syncthreads();

        // ---- tails: tid<128 -> L0, tid in [128,256) -> L1 ----
        if (tid < 128) {
            if (s < TT) {
                const int b = tid & 31, jj = tid >> 5;
                const int j = j0 + jj;
                float pre[4] = {pre0, pre1, pre2, pre3};
                float gate[4];
                #pragma unroll
                for (int g = 0; g < 4; g++) {
                    const int rr = g * 4 + jj;
                    float4 q0 = *reinterpret_cast<const float4*>(&red0[(rr * 32 + b) * 4]);
                    gate[g] = ((q0.x + q0.y) + (q0.z + q0.w)) + pre[g] + bs0[rr];
                }
                float ig = sigf(gate[0]);
                float fg = sigf(gate[1]);
                float cg = tanhf_(gate[2]);
                float og = sigf(gate[3]);
                float c_new = fmaf(fg, cs0[tid], ig * cg);
                float h_new = og * tanhf_(c_new);
                cs0[tid] = c_new;
                g_hbuf0[(s + 1) & 1][j * BB + b] = h_new;
                if (s == TT - 1) {
                    hc_out[(size_t)0 * BB * HH + b * HH + j] = h_new;
                    hc_out[(size_t)2 * BB * HH + b * HH + j] = c_new;
                }
            }
        } else if (tid < 256) {
            if (s >= 1) {
                const int tt_ = tid - 128;
                const int b = tt_ & 31, jj = tt_ >> 5;
                const int j = j0 + jj;
                const int t = s - 1;
                float gate[4];
                #pragma unroll
                for (int g = 0; g < 4; g++) {
                    const int rr = g * 4 + jj;
                    const float4* rp = reinterpret_cast<const float4*>(&red1[(rr * 32 + b) * 8]);
                    float4 q0 = rp[0], q1 = rp[1];
                    gate[g] = ((q0.x + q0.y) + (q0.z + q0.w))
                            + ((q1.x + q1.y) + (q1.z + q1.w)) + bs1[rr];
                }
                float ig = sigf(gate[0]);
                float fg = sigf(gate[1]);
                float cg = tanhf_(gate[2]);
                float og = sigf(gate[3]);
                float c_new = fmaf(fg, cs1[tt_], ig * cg);
                float h_new = og * tanhf_(c_new);
                cs1[tt_] = c_new;
                g_hbuf1[s & 1][j * BB + b] = h_new;
                yout[((size_t)b * TT + t) * HH + j] = h_new;
                if (t == TT - 1) {
                    hc_out[(size_t)1 * BB * HH + b * HH + j] = h_new;
                    hc_out[(size_t)3 * BB * HH + b * HH + j] = c_new;
                }
            }
        }

        // ---- parallel-detection global barrier ----
        if (s < TT) {
            const unsigned e = (unsigned)(s + 1);
            __syncthreads();   // all h stores of this CTA done
            if (tid == 0)      // announce arrival on own 128B line
                asm volatile("st.release.gpu.u32 [%0], %1;"
                             :: "l"(&g_flags[bid * 32]), "r"(e) : "memory");
            if (bid == 0) {
                if (tid < NCTA) {   // parallel detection, one flag per thread
                    unsigned v;
                    do {
                        asm volatile("ld.acquire.gpu.u32 %0, [%1];"
                                     : "=r"(v) : "l"(&g_flags[tid * 32]) : "memory");
                    } while (v < e);
                }
                __syncthreads();
                if (tid == 0)
                    asm volatile("st.release.gpu.u32 [%0], %1;"
                                 :: "l"(&g_epoch), "r"(e) : "memory");
            } else {
                if (tid == 0) {
                    unsigned v;
                    do {
                        asm volatile("ld.acquire.gpu.u32 %0, [%1];"
                                     : "=r"(v) : "l"(&g_epoch) : "memory");
                    } while (v < e);
                }
                __syncthreads();
            }
        }
    }
}

extern "C" void kernel_launch(void* const* d_in, const int* in_sizes, int n_in,
                              void* d_out, int out_size)
{
    (void)in_sizes; (void)n_in; (void)out_size;
    const float* x   = (const float*)d_in[0];
    const float* Wi0 = (const float*)d_in[1];
    const float* bi0 = (const float*)d_in[2];
    const float* Wh0 = (const float*)d_in[3];
    const float* bh0 = (const float*)d_in[4];
    const float* Wi1 = (const float*)d_in[5];
    const float* bi1 = (const float*)d_in[6];
    const float* Wh1 = (const float*)d_in[7];
    const float* bh1 = (const float*)d_in[8];
    float* out = (float*)d_out;

    float* i2h_p;
    cudaGetSymbolAddress((void**)&i2h_p, g_i2h);

    const int SMEM = (512*16 + 1024*16 + 16*32*4 + 16*32*8 + 16 + 16 + 128 + 128)
                     * (int)sizeof(float);
    cudaFuncSetAttribute(lstm_fused_kernel,
                         cudaFuncAttributeMaxDynamicSharedMemorySize, SMEM);

    dim3 ggrid(G4 / 128, (BB * TT) / 128);
    float* hc = out + (size_t)BB * TT * HH;

    gemm_kernel<<<ggrid, 256>>>(x, Wi0, bi0, i2h_p);          // L0 i2h only
    init_state_kernel<<<64, 256>>>();
    lstm_fused_kernel<<<NCTA, NTHR, SMEM>>>(Wh0, bh0, Wi1, bi1, Wh1, bh1,
                                            i2h_p, out, hc);
}

// round 8
// speedup vs baseline: 2.0094x; 1.1835x over previous
#include <cuda_runtime.h>
#include <cstddef>

#define BB 32
#define TT 2048
#define DD 512
#define HH 512
#define G4 2048
#define NCTA 128
#define JC 4
#define NTHR 384

// Scratch (device globals are the sanctioned allocation-free scratch)
__device__ float g_i2h[(size_t)BB * TT * G4];   // 512 MB, layer-0 i2h
__device__ float g_hbuf0[2][HH * BB];           // double-buffered h0, [j][b]
__device__ float g_hbuf1[2][HH * BB];           // double-buffered h1, [j][b]
__device__ unsigned g_flags[NCTA * 32];         // per-CTA arrival, own 128B line

__global__ void init_state_kernel() {
    int i = blockIdx.x * blockDim.x + threadIdx.x;
    if (i < HH * BB) { g_hbuf0[0][i] = 0.f; g_hbuf1[0][i] = 0.f; }
    if (i < NCTA * 32) g_flags[i] = 0u;
}

__device__ __forceinline__ float sigf(float x) { return 1.f / (1.f + __expf(-x)); }
__device__ __forceinline__ float tanhf_(float x) {
    x = fminf(15.f, fmaxf(-15.f, x));
    float e = __expf(2.f * x);
    return (e - 1.f) / (e + 1.f);
}

// C[M,2048] = A[M,512] @ W[2048,512]^T + bias ; M = 65536, tiles 128x128x16.
__global__ __launch_bounds__(256, 2) void gemm_kernel(
    const float* __restrict__ A, const float* __restrict__ W,
    const float* __restrict__ bias, float* __restrict__ C)
{
    __shared__ float As[2][16][128];
    __shared__ float Ws[2][16][128];
    const int tid = threadIdx.x;
    const int tx = tid & 15, ty = tid >> 4;
    const int m0 = blockIdx.y * 128, n0 = blockIdx.x * 128;

    float acc[8][8];
    #pragma unroll
    for (int i = 0; i < 8; i++)
        #pragma unroll
        for (int j = 0; j < 8; j++) acc[i][j] = 0.f;

    const int lr = tid >> 1;
    const int lc = (tid & 1) * 2;
    const float* Arow = A + (size_t)(m0 + lr) * DD;
    const float* Wrow = W + (size_t)(n0 + lr) * DD;

    float4 ra0, ra1, rw0, rw1;
    ra0 = *reinterpret_cast<const float4*>(&Arow[lc * 4]);
    ra1 = *reinterpret_cast<const float4*>(&Arow[(lc + 1) * 4]);
    rw0 = *reinterpret_cast<const float4*>(&Wrow[lc * 4]);
    rw1 = *reinterpret_cast<const float4*>(&Wrow[(lc + 1) * 4]);
    {
        int c0 = lc, c1 = lc + 1;
        As[0][c0*4+0][lr] = ra0.x; As[0][c0*4+1][lr] = ra0.y;
        As[0][c0*4+2][lr] = ra0.z; As[0][c0*4+3][lr] = ra0.w;
        As[0][c1*4+0][lr] = ra1.x; As[0][c1*4+1][lr] = ra1.y;
        As[0][c1*4+2][lr] = ra1.z; As[0][c1*4+3][lr] = ra1.w;
        Ws[0][c0*4+0][lr] = rw0.x; Ws[0][c0*4+1][lr] = rw0.y;
        Ws[0][c0*4+2][lr] = rw0.z; Ws[0][c0*4+3][lr] = rw0.w;
        Ws[0][c1*4+0][lr] = rw1.x; Ws[0][c1*4+1][lr] = rw1.y;
        Ws[0][c1*4+2][lr] = rw1.z; Ws[0][c1*4+3][lr] = rw1.w;
    }
    __syncthreads();

    int p = 0;
    for (int k0 = 0; k0 < DD; k0 += 16) {
        const bool more = (k0 + 16 < DD);
        if (more) {
            ra0 = *reinterpret_cast<const float4*>(&Arow[k0 + 16 + lc * 4]);
            ra1 = *reinterpret_cast<const float4*>(&Arow[k0 + 16 + (lc + 1) * 4]);
            rw0 = *reinterpret_cast<const float4*>(&Wrow[k0 + 16 + lc * 4]);
            rw1 = *reinterpret_cast<const float4*>(&Wrow[k0 + 16 + (lc + 1) * 4]);
        }
        #pragma unroll
        for (int k = 0; k < 16; k++) {
            float4 a0 = *reinterpret_cast<const float4*>(&As[p][k][ty * 8]);
            float4 a1 = *reinterpret_cast<const float4*>(&As[p][k][ty * 8 + 4]);
            float4 b0 = *reinterpret_cast<const float4*>(&Ws[p][k][tx * 8]);
            float4 b1 = *reinterpret_cast<const float4*>(&Ws[p][k][tx * 8 + 4]);
            float av[8] = {a0.x,a0.y,a0.z,a0.w,a1.x,a1.y,a1.z,a1.w};
            float bv[8] = {b0.x,b0.y,b0.z,b0.w,b1.x,b1.y,b1.z,b1.w};
            #pragma unroll
            for (int i = 0; i < 8; i++)
                #pragma unroll
                for (int j = 0; j < 8; j++)
                    acc[i][j] = fmaf(av[i], bv[j], acc[i][j]);
        }
        if (more) {
            int q = 1 - p;
            int c0 = lc, c1 = lc + 1;
            As[q][c0*4+0][lr] = ra0.x; As[q][c0*4+1][lr] = ra0.y;
            As[q][c0*4+2][lr] = ra0.z; As[q][c0*4+3][lr] = ra0.w;
            As[q][c1*4+0][lr] = ra1.x; As[q][c1*4+1][lr] = ra1.y;
            As[q][c1*4+2][lr] = ra1.z; As[q][c1*4+3][lr] = ra1.w;
            Ws[q][c0*4+0][lr] = rw0.x; Ws[q][c0*4+1][lr] = rw0.y;
            Ws[q][c0*4+2][lr] = rw0.z; Ws[q][c0*4+3][lr] = rw0.w;
            Ws[q][c1*4+0][lr] = rw1.x; Ws[q][c1*4+1][lr] = rw1.y;
            Ws[q][c1*4+2][lr] = rw1.z; Ws[q][c1*4+3][lr] = rw1.w;
            __syncthreads();
            p = q;
        }
    }

    float4 bs0 = *reinterpret_cast<const float4*>(&bias[n0 + tx*8]);
    float4 bs1 = *reinterpret_cast<const float4*>(&bias[n0 + tx*8 + 4]);
    #pragma unroll
    for (int i = 0; i < 8; i++) {
        size_t row = (size_t)(m0 + ty*8 + i) * G4 + n0 + tx*8;
        float4 o0 = make_float4(acc[i][0]+bs0.x, acc[i][1]+bs0.y, acc[i][2]+bs0.z, acc[i][3]+bs0.w);
        float4 o1 = make_float4(acc[i][4]+bs1.x, acc[i][5]+bs1.y, acc[i][6]+bs1.z, acc[i][7]+bs1.w);
        *reinterpret_cast<float4*>(&C[row])     = o0;
        *reinterpret_cast<float4*>(&C[row + 4]) = o1;
    }
}

// Fused two-layer pipelined recurrence, spatial phase split.
// 384 threads / 12 warps: warps 0-3 -> L0 (t=s), warps 4-11 -> L1 (t=s-1).
// 2049 wall steps; ONE all-to-all flag barrier each (no epoch hop).
__global__ __launch_bounds__(NTHR, 1) void lstm_fused_kernel(
    const float* __restrict__ Wh0, const float* __restrict__ bh0,
    const float* __restrict__ Wi1, const float* __restrict__ bi1,
    const float* __restrict__ Wh1, const float* __restrict__ bh1,
    const float* __restrict__ i2h, float* __restrict__ yout,
    float* __restrict__ hc_out)
{
    extern __shared__ float sm[];
    float* ws0  = sm;                   // 512*16
    float* ws1  = ws0 + 512 * 16;       // 1024*16
    float* red0 = ws1 + 1024 * 16;      // 16*32*4
    float* red1 = red0 + 16 * 32 * 4;   // 16*32*8
    float* pres = red1 + 16 * 32 * 8;   // 128 float4 = 512 floats
    float* bs0  = pres + 512;           // 16
    float* bs1  = bs0 + 16;             // 16
    float* cs0  = bs1 + 16;             // 128
    float* cs1  = cs0 + 128;            // 128

    const int tid = threadIdx.x;
    const int bid = blockIdx.x;
    const int j0 = bid * JC;

    // ---- stage weights transposed: ws[k*16 + rl], rl = g*4 + jj ----
    for (int idx = tid; idx < 512 * 16; idx += NTHR) {
        int k = idx >> 4, rl = idx & 15;
        int g = rl >> 2, jj = rl & 3;
        ws0[idx] = Wh0[(size_t)(g * HH + j0 + jj) * HH + k];
    }
    for (int idx = tid; idx < 1024 * 16; idx += NTHR) {
        int k = idx >> 4, rl = idx & 15;
        int g = rl >> 2, jj = rl & 3;
        ws1[idx] = (k < 512)
            ? Wi1[(size_t)(g * HH + j0 + jj) * HH + k]
            : Wh1[(size_t)(g * HH + j0 + jj) * HH + (k - 512)];
    }
    if (tid < 16) {
        int gg = tid >> 2, jx = tid & 3;
        bs0[tid] = bh0[gg * HH + j0 + jx];
        bs1[tid] = bi1[gg * HH + j0 + jx] + bh1[gg * HH + j0 + jx];
    }
    if (tid < 128) { cs0[tid] = 0.f; cs1[tid] = 0.f; }
    __syncthreads();

    const int w  = tid >> 5;           // warp 0..11
    const int rt = (tid >> 3) & 3;     // row quad
    const int bt = tid & 7;            // batch quad
    const float4* ws0_4 = reinterpret_cast<const float4*>(ws0);
    const float4* ws1_4 = reinterpret_cast<const float4*>(ws1);
    float4* pres4 = reinterpret_cast<float4*>(pres);

    for (int s = 0; s <= TT; s++) {
        // coalesced i2h prefetch: thread (b,g) -> one float4 (4 consecutive j)
        float4 preq = make_float4(0.f, 0.f, 0.f, 0.f);
        if (tid < 128 && s < TT) {
            const int b_ = tid & 31, g_ = tid >> 5;
            preq = __ldcg(reinterpret_cast<const float4*>(
                i2h + ((size_t)b_ * TT + s) * G4 + (g_ << 9) + j0));
        }

        // ---- FMA phase: one 128-k loop per warp ----
        {
            const float4* src4 = nullptr;
            const float4* wsrc4 = nullptr;
            int kb = 0, kw = 0;
            bool active = false;
            if (w < 4) {                 // L0, t = s
                if (s < TT) {
                    active = true;
                    src4 = reinterpret_cast<const float4*>(g_hbuf0[s & 1]);
                    kb = w * 128;  kw = kb;  wsrc4 = ws0_4;
                }
            } else if (s >= 1) {         // L1, t = s-1
                active = true;
                wsrc4 = ws1_4;
                if (w < 8) {             // y0(t) part
                    src4 = reinterpret_cast<const float4*>(g_hbuf0[s & 1]);
                    kb = (w - 4) * 128;  kw = kb;
                } else {                 // h1(t-1) part
                    src4 = reinterpret_cast<const float4*>(g_hbuf1[(s - 1) & 1]);
                    kb = (w - 8) * 128;  kw = 512 + kb;
                }
            }
            if (active) {
                float acc[4][4];
                #pragma unroll
                for (int ri = 0; ri < 4; ri++)
                    #pragma unroll
                    for (int bi = 0; bi < 4; bi++) acc[ri][bi] = 0.f;
                #pragma unroll 4
                for (int c = 0; c < 16; c++) {        // 16 chunks x 8 k
                    float4 hp[8];
                    #pragma unroll
                    for (int i = 0; i < 8; i++)
                        hp[i] = __ldcg(&src4[(size_t)(kb + c * 8 + i) * 8 + bt]);
                    #pragma unroll
                    for (int i = 0; i < 8; i++) {
                        float4 wv = wsrc4[(kw + c * 8 + i) * 4 + rt];
                        acc[0][0] = fmaf(wv.x, hp[i].x, acc[0][0]);
                        acc[0][1] = fmaf(wv.x, hp[i].y, acc[0][1]);
                        acc[0][2] = fmaf(wv.x, hp[i].z, acc[0][2]);
                        acc[0][3] = fmaf(wv.x, hp[i].w, acc[0][3]);
                        acc[1][0] = fmaf(wv.y, hp[i].x, acc[1][0]);
                        acc[1][1] = fmaf(wv.y, hp[i].y, acc[1][1]);
                        acc[1][2] = fmaf(wv.y, hp[i].z, acc[1][2]);
                        acc[1][3] = fmaf(wv.y, hp[i].w, acc[1][3]);
                        acc[2][0] = fmaf(wv.z, hp[i].x, acc[2][0]);
                        acc[2][1] = fmaf(wv.z, hp[i].y, acc[2][1]);
                        acc[2][2] = fmaf(wv.z, hp[i].z, acc[2][2]);
                        acc[2][3] = fmaf(wv.z, hp[i].w, acc[2][3]);
                        acc[3][0] = fmaf(wv.w, hp[i].x, acc[3][0]);
                        acc[3][1] = fmaf(wv.w, hp[i].y, acc[3][1]);
                        acc[3][2] = fmaf(wv.w, hp[i].z, acc[3][2]);
                        acc[3][3] = fmaf(wv.w, hp[i].w, acc[3][3]);
                    }
                }
                if (w < 4) {
                    #pragma unroll
                    for (int ri = 0; ri < 4; ri++)
                        #pragma unroll
                        for (int bi = 0; bi < 4; bi++)
                            red0[((rt * 4 + ri) * 32 + bt * 4 + bi) * 4 + w] = acc[ri][bi];
                } else {
                    #pragma unroll
                    for (int ri = 0; ri < 4; ri++)
                        #pragma unroll
                        for (int bi = 0; bi < 4; bi++)
                            red1[((rt * 4 + ri) * 32 + bt * 4 + bi) * 8 + (w - 4)] = acc[ri][bi];
                }
            }
        }
        // park prefetched i2h in smem (data long since arrived -> no stall)
        if (tid < 128 && s < TT) pres4[tid] = preq;
        __syncthreads();

        // ---- tails: tid<128 -> L0, tid in [128,256) -> L1 ----
        float   y_val = 0.f;           // deferred y1 store (L1 tail)
        size_t  y_idx = 0;
        bool    y_pend = false;

        if (tid < 128) {
            if (s < TT) {
                const int b = tid & 31, jj = tid >> 5;
                const int j = j0 + jj;
                float gate[4];
                #pragma unroll
                for (int g = 0; g < 4; g++) {
                    const int rr = g * 4 + jj;
                    float4 q0 = *reinterpret_cast<const float4*>(&red0[(rr * 32 + b) * 4]);
                    float pre = pres[(g * 32 + b) * 4 + jj];
                    gate[g] = ((q0.x + q0.y) + (q0.z + q0.w)) + pre + bs0[rr];
                }
                float ig = sigf(gate[0]);
                float fg = sigf(gate[1]);
                float cg = tanhf_(gate[2]);
                float og = sigf(gate[3]);
                float c_new = fmaf(fg, cs0[tid], ig * cg);
                float h_new = og * tanhf_(c_new);
                cs0[tid] = c_new;
                g_hbuf0[(s + 1) & 1][j * BB + b] = h_new;
                if (s == TT - 1) {
                    hc_out[(size_t)0 * BB * HH + b * HH + j] = h_new;
                    hc_out[(size_t)2 * BB * HH + b * HH + j] = c_new;
                }
            }
        } else if (tid < 256) {
            if (s >= 1) {
                const int tt_ = tid - 128;
                const int b = tt_ & 31, jj = tt_ >> 5;
                const int j = j0 + jj;
                const int t = s - 1;
                float gate[4];
                #pragma unroll
                for (int g = 0; g < 4; g++) {
                    const int rr = g * 4 + jj;
                    const float4* rp = reinterpret_cast<const float4*>(&red1[(rr * 32 + b) * 8]);
                    float4 q0 = rp[0], q1 = rp[1];
                    gate[g] = ((q0.x + q0.y) + (q0.z + q0.w))
                            + ((q1.x + q1.y) + (q1.z + q1.w)) + bs1[rr];
                }
                float ig = sigf(gate[0]);
                float fg = sigf(gate[1]);
                float cg = tanhf_(gate[2]);
                float og = sigf(gate[3]);
                float c_new = fmaf(fg, cs1[tt_], ig * cg);
                float h_new = og * tanhf_(c_new);
                cs1[tt_] = c_new;
                g_hbuf1[s & 1][j * BB + b] = h_new;
                y_val = h_new;
                y_idx = ((size_t)b * TT + t) * HH + j;
                if (s < TT) {
                    y_pend = true;             // store after barrier announce
                } else {
                    yout[y_idx] = h_new;       // last step: no barrier follows
                }
                if (t == TT - 1) {
                    hc_out[(size_t)1 * BB * HH + b * HH + j] = h_new;
                    hc_out[(size_t)3 * BB * HH + b * HH + j] = c_new;
                }
            }
        }

        // ---- all-to-all flag barrier ----
        if (s < TT) {
            const unsigned e = (unsigned)(s + 1);
            __syncthreads();   // all h stores of this CTA done
            if (tid == 0)      // announce arrival on own 128B line
                asm volatile("st.release.gpu.u32 [%0], %1;"
                             :: "l"(&g_flags[bid * 32]), "r"(e) : "memory");
            if (y_pend) yout[y_idx] = y_val;   // overlap DRAM store w/ wait
            if (tid < NCTA) {  // every CTA polls every flag in parallel
                unsigned v;
                do {
                    asm volatile("ld.acquire.gpu.u32 %0, [%1];"
                                 : "=r"(v) : "l"(&g_flags[tid * 32]) : "memory");
                } while (v < e);
            }
            __syncthreads();
        }
    }
}

extern "C" void kernel_launch(void* const* d_in, const int* in_sizes, int n_in,
                              void* d_out, int out_size)
{
    (void)in_sizes; (void)n_in; (void)out_size;
    const float* x   = (const float*)d_in[0];
    const float* Wi0 = (const float*)d_in[1];
    const float* bi0 = (const float*)d_in[2];
    const float* Wh0 = (const float*)d_in[3];
    const float* bh0 = (const float*)d_in[4];
    const float* Wi1 = (const float*)d_in[5];
    const float* bi1 = (const float*)d_in[6];
    const float* Wh1 = (const float*)d_in[7];
    const float* bh1 = (const float*)d_in[8];
    float* out = (float*)d_out;

    float* i2h_p;
    cudaGetSymbolAddress((void**)&i2h_p, g_i2h);

    const int SMEM = (512*16 + 1024*16 + 16*32*4 + 16*32*8 + 512
                      + 16 + 16 + 128 + 128) * (int)sizeof(float);
    cudaFuncSetAttribute(lstm_fused_kernel,
                         cudaFuncAttributeMaxDynamicSharedMemorySize, SMEM);

    dim3 ggrid(G4 / 128, (BB * TT) / 128);
    float* hc = out + (size_t)BB * TT * HH;

    gemm_kernel<<<ggrid, 256>>>(x, Wi0, bi0, i2h_p);          // L0 i2h only
    init_state_kernel<<<64, 256>>>();
    lstm_fused_kernel<<<NCTA, NTHR, SMEM>>>(Wh0, bh0, Wi1, bi1, Wh1, bh1,
                                            i2h_p, out, hc);
}